// round 12
// baseline (speedup 1.0000x reference)
#include <cuda_runtime.h>

// Integrate-and-fire scan fused with per-timestep 64x512 transpose.
//   v += x[t]; if (v > 2.0f) { spike[t] = 1; v = 0; }  (membrane reset at t=100)
//
// R8 = R6/R7 memory patterns (wavefront-ideal 32x32 tile: warp LDG.64/STG.64
// = 2 full 128B lines each; scalar conflict-free STS/LDS; double-buffered
// smem) with GROUP=10: one barrier per 10 timesteps (10 total, was 25).
// Each phase front-issues 10 independent LDG.64 per thread (80B in flight,
// consumed one full phase later), so latency hiding is structural rather
// than dependent on ptxas keeping a prefetch queue alive.
// Smem 84.5KB -> dynamic + cudaFuncSetAttribute.

namespace {
constexpr int kH     = 64;
constexpr int kWC    = 512;                      // W*C
constexpr int kChunk = 100;
constexpr int kNPB   = kH * kWC;                 // 32768 neurons / batch
constexpr long long kBS = 200LL * kNPB;          // batch stride (elements)
constexpr int kGroup = 10;                       // timesteps per barrier
constexpr int kNG    = kChunk / kGroup;          // 10
constexpr float kTh  = 2.0f;
// smem slice: [2][kGroup][32][33] floats
constexpr int kSliceRow = 33;
constexpr int kSliceT   = 32 * kSliceRow;        // per t-slice
constexpr int kSliceBuf = kGroup * kSliceT;      // per buffer
constexpr int kSmemFloats = 2 * kSliceBuf;
constexpr int kSmemBytes  = kSmemFloats * 4;     // 84480
}

__global__ void __launch_bounds__(512)
integrator_kernel(const float* __restrict__ in, float* __restrict__ out) {
    extern __shared__ float sm[];                // [2][10][32][33]

    const int tid = threadIdx.x;
    const int row = tid >> 4;                    // 0..31
    const int p   = tid & 15;                    // 0..15
    const int sh2 = p * 2;
    const int wc0 = blockIdx.x * 32;
    const int h0  = blockIdx.y * 32;
    const int b   = blockIdx.z >> 1;
    const int t0  = (blockIdx.z & 1) * kChunk;

    const long long base = b * kBS + (long long)t0 * kNPB;

    // Load: thread owns neurons (h0+row, wc0+2p, wc0+2p+1).
    // Warp LDG.64 = 2 h-rows x 16 float2 = 2 full 128B lines (ideal).
    const float* __restrict__ pin =
        in + base + (long long)(h0 + row) * kWC + wc0 + sh2;
    // Store: thread writes float2 of h at wc = wc0+row.
    // Warp STG.64 = 2 wc-rows x 16 float2 = 2 full 128B lines (ideal).
    float* __restrict__ pout =
        out + base + (long long)(wc0 + row) * kH + h0 + sh2;

    // smem addresses (float offsets)
    const int wbase = row * kSliceRow + sh2;         // compute-side STS
    const int rbase = sh2 * kSliceRow + row;         // store-side LDS

    float v0 = 0.f, v1 = 0.f;

    for (int gi = 0; gi < kNG; ++gi) {
        const int pb = (gi & 1) * kSliceBuf;

        // Front-batch all 10 independent loads of this phase.
        float2 q[kGroup];
        const float* pg = pin + (long long)gi * kGroup * kNPB;
#pragma unroll
        for (int g = 0; g < kGroup; ++g)
            q[g] = *reinterpret_cast<const float2*>(pg + (long long)g * kNPB);

#pragma unroll
        for (int g = 0; g < kGroup; ++g) {
            float s0, s1;
            v0 += q[g].x; s0 = (v0 > kTh) ? 1.f : 0.f; v0 = (v0 > kTh) ? 0.f : v0;
            v1 += q[g].y; s1 = (v1 > kTh) ? 1.f : 0.f; v1 = (v1 > kTh) ? 0.f : v1;
            // banks (row + 2p)/(row + 2p + 1): half-warps on opposite
            // parities -> 32 distinct banks, conflict-free.
            sm[pb + g * kSliceT + wbase + 0] = s0;
            sm[pb + g * kSliceT + wbase + 1] = s1;
        }
        __syncthreads();   // single barrier per phase; double buffer protects reuse

        float* po = pout + (long long)gi * kGroup * kNPB;
#pragma unroll
        for (int g = 0; g < kGroup; ++g) {
            float2 o;
            o.x = sm[pb + g * kSliceT + rbase];              // bank (2p+row)
            o.y = sm[pb + g * kSliceT + rbase + kSliceRow];  // bank (2p+1+row)
            *reinterpret_cast<float2*>(po + (long long)g * kNPB) = o;
        }
    }
}

extern "C" void kernel_launch(void* const* d_in, const int* in_sizes, int n_in,
                              void* d_out, int out_size) {
    (void)in_sizes; (void)n_in; (void)out_size;
    const float* in = (const float*)d_in[0];
    float* out = (float*)d_out;
    static bool attr_done = false;
    if (!attr_done) {
        cudaFuncSetAttribute(integrator_kernel,
                             cudaFuncAttributeMaxDynamicSharedMemorySize,
                             kSmemBytes);
        attr_done = true;
    }
    dim3 grid(kWC / 32, kH / 32, 4 * 2);   // 16 x 2 x 8 = 256 blocks x 512 thr
    integrator_kernel<<<grid, 512, kSmemBytes>>>(in, out);
}

// round 13
// speedup vs baseline: 1.2833x; 1.2833x over previous
#include <cuda_runtime.h>

// Integrate-and-fire scan fused with per-timestep 64x512 transpose.
//   v += x[t]; if (v > 2.0f) { spike[t] = 1; v = 0; }  (membrane reset at t=100)
//
// R9 = R7 (wavefront-ideal 32x32 tile: warp LDG.64/STG.64 = 2 full 128B
// lines each direction; scalar conflict-free STS/LDS; double-buffered smem,
// 1 barrier per 4-timestep group; distance-2 prefetch queues q0/q1) with the
// load-sinking defeated: an empty asm "liveness pin" after each refill
// forces ptxas to issue all 4 queue loads at that point (R7/R8 showed
// regs=32 -> ptxas sank queue loads into the consume loop, MLP~2).
// Streaming cache hints (__ldcs/__stcs): both streams are touch-once.
// __launch_bounds__(512,2) raises the reg ceiling to 64 (2 CTAs/SM kept).

namespace {
constexpr int kH     = 64;
constexpr int kWC    = 512;                      // W*C
constexpr int kChunk = 100;
constexpr int kNPB   = kH * kWC;                 // 32768 neurons / batch
constexpr long long kBS = 200LL * kNPB;          // batch stride (elements)
constexpr int kGroup = 4;                        // timesteps per barrier
constexpr int kNG    = kChunk / kGroup;          // 25
constexpr float kTh  = 2.0f;
}

// Force all 8 queue floats live at this program point: ptxas must have
// issued the 4 LDG.64s feeding them before it. Zero-cost otherwise.
__device__ __forceinline__ void pin_queue(float2 (&q)[kGroup]) {
    asm volatile("" : "+f"(q[0].x), "+f"(q[0].y),
                      "+f"(q[1].x), "+f"(q[1].y),
                      "+f"(q[2].x), "+f"(q[2].y),
                      "+f"(q[3].x), "+f"(q[3].y));
}

__global__ void __launch_bounds__(512, 2)
integrator_kernel(const float* __restrict__ in, float* __restrict__ out) {
    __shared__ float sm[2][kGroup][32][33];      // [buf][t][h-row][wc], pad 33

    const int tid = threadIdx.x;
    const int row = tid >> 4;                    // 0..31
    const int p   = tid & 15;                    // 0..15
    const int sh2 = p * 2;
    const int wc0 = blockIdx.x * 32;
    const int h0  = blockIdx.y * 32;
    const int b   = blockIdx.z >> 1;
    const int t0  = (blockIdx.z & 1) * kChunk;

    const long long base = b * kBS + (long long)t0 * kNPB;

    // Load: thread owns neurons (h0+row, wc0+2p, wc0+2p+1).
    // Warp LDG.64 = 2 h-rows x 16 float2 = 2 full 128B lines (ideal).
    const float* __restrict__ pin =
        in + base + (long long)(h0 + row) * kWC + wc0 + sh2;
    // Store: thread writes float2 of h at wc = wc0+row.
    // Warp STG.64 = 2 wc-rows x 16 float2 = 2 full 128B lines (ideal).
    float* __restrict__ pout =
        out + base + (long long)(wc0 + row) * kH + h0 + sh2;

    float v0 = 0.f, v1 = 0.f;

    float2 q0[kGroup], q1[kGroup];
#pragma unroll
    for (int g = 0; g < kGroup; ++g)
        q0[g] = __ldcs(reinterpret_cast<const float2*>(
                    pin + (long long)(0 * kGroup + g) * kNPB));
    pin_queue(q0);
#pragma unroll
    for (int g = 0; g < kGroup; ++g)
        q1[g] = __ldcs(reinterpret_cast<const float2*>(
                    pin + (long long)(1 * kGroup + g) * kNPB));
    pin_queue(q1);

    // One phase: consume q (loaded 2 phases ago), refill q with loads for
    // phase gi+2 (pinned -> issued now), barrier, store transposed spikes.
    auto process = [&](int gi, float2 (&q)[kGroup]) {
        const int pb = gi & 1;
        float2 held[kGroup];
#pragma unroll
        for (int g = 0; g < kGroup; ++g) held[g] = q[g];

        // Refill queue for phase gi+2; pin forces the 4 LDG.64s to issue
        // here, two full phases before their consumption.
        if (gi + 2 < kNG) {
            const float* pn = pin + (long long)(gi + 2) * kGroup * kNPB;
#pragma unroll
            for (int g = 0; g < kGroup; ++g)
                q[g] = __ldcs(reinterpret_cast<const float2*>(
                            pn + (long long)g * kNPB));
            pin_queue(q);
        }

#pragma unroll
        for (int g = 0; g < kGroup; ++g) {
            float s0, s1;
            v0 += held[g].x; s0 = (v0 > kTh) ? 1.f : 0.f; v0 = (v0 > kTh) ? 0.f : v0;
            v1 += held[g].y; s1 = (v1 > kTh) ? 1.f : 0.f; v1 = (v1 > kTh) ? 0.f : v1;
            // banks (row + 2p)/(row + 2p + 1): half-warps on opposite
            // parities -> 32 distinct banks, conflict-free.
            sm[pb][g][row][sh2 + 0] = s0;
            sm[pb][g][row][sh2 + 1] = s1;
        }
        __syncthreads();   // single barrier; double buffer protects reuse

        float* po = pout + (long long)gi * kGroup * kNPB;
#pragma unroll
        for (int g = 0; g < kGroup; ++g) {
            float2 o;
            o.x = sm[pb][g][sh2 + 0][row];   // bank (2p + row): conflict-free
            o.y = sm[pb][g][sh2 + 1][row];   // bank (2p + 1 + row)
            __stcs(reinterpret_cast<float2*>(po + (long long)g * kNPB), o);
        }
    };

#pragma unroll 1
    for (int gi = 0; gi < kNG - 1; gi += 2) {    // 12 pairs: phases 0..23
        process(gi,     q0);
        process(gi + 1, q1);
    }
    process(kNG - 1, q0);                        // phase 24
}

extern "C" void kernel_launch(void* const* d_in, const int* in_sizes, int n_in,
                              void* d_out, int out_size) {
    (void)in_sizes; (void)n_in; (void)out_size;
    const float* in = (const float*)d_in[0];
    float* out = (float*)d_out;
    dim3 grid(kWC / 32, kH / 32, 4 * 2);   // 16 x 2 x 8 = 256 blocks x 512 thr
    integrator_kernel<<<grid, 512>>>(in, out);
}

// round 16
// speedup vs baseline: 1.4843x; 1.1566x over previous
#include <cuda_runtime.h>

// Integrate-and-fire scan fused with per-timestep 64x512 transpose.
//   v += x[t]; if (v > 2.0f) { spike[t] = 1; v = 0; }  (membrane reset at t=100)
//
// R10 = R7 (best: wavefront-ideal 32x32 tile, warp LDG.64/STG.64 = 2 full
// 128B lines both directions, scalar conflict-free STS/LDS pad-33,
// distance-2 register queues, plain loads) with BARRIERS HALVED: two
// 4-timestep phases share one __syncthreads() using 4 smem buffers.
// Pair p writes bufs {(p&1)*2, (p&1)*2+1}; pair p+2's overwrite of a buffer
// is separated from pair p's reads by pair p+1's barrier. 13 barriers vs 25.
// Smem 67.6KB -> dynamic + host-side attribute (2 CTAs/SM preserved).

namespace {
constexpr int kH     = 64;
constexpr int kWC    = 512;                      // W*C
constexpr int kChunk = 100;
constexpr int kNPB   = kH * kWC;                 // 32768 neurons / batch
constexpr long long kBS = 200LL * kNPB;          // batch stride (elements)
constexpr int kGroup = 4;                        // timesteps per phase
constexpr int kNG    = kChunk / kGroup;          // 25 phases
constexpr float kTh  = 2.0f;
constexpr int kTSlice  = 32 * 33;                // floats per t-slice
constexpr int kBufSize = kGroup * kTSlice;       // floats per buffer
constexpr int kSmemBytes = 4 * kBufSize * 4;     // 4 buffers = 67584 B
}

__global__ void __launch_bounds__(512, 2)
integrator_kernel(const float* __restrict__ in, float* __restrict__ out) {
    extern __shared__ float sm[];                // [4][kGroup][32][33]

    const int tid = threadIdx.x;
    const int row = tid >> 4;                    // 0..31
    const int p   = tid & 15;                    // 0..15
    const int sh2 = p * 2;
    const int wc0 = blockIdx.x * 32;
    const int h0  = blockIdx.y * 32;
    const int b   = blockIdx.z >> 1;
    const int t0  = (blockIdx.z & 1) * kChunk;

    const long long base = b * kBS + (long long)t0 * kNPB;

    // Load: thread owns neurons (h0+row, wc0+2p, wc0+2p+1).
    // Warp LDG.64 = 2 h-rows x 16 float2 = 2 full 128B lines (ideal).
    const float* __restrict__ pin =
        in + base + (long long)(h0 + row) * kWC + wc0 + sh2;
    // Store: thread writes float2 of h at wc = wc0+row.
    // Warp STG.64 = 2 wc-rows x 16 float2 = 2 full 128B lines (ideal).
    float* __restrict__ pout =
        out + base + (long long)(wc0 + row) * kH + h0 + sh2;

    const int wbase = row * 33 + sh2;            // compute-side STS offset
    const int rbase = sh2 * 33 + row;            // store-side  LDS offset

    float v0 = 0.f, v1 = 0.f;

    float2 q0[kGroup], q1[kGroup];
#pragma unroll
    for (int g = 0; g < kGroup; ++g) {
        q0[g] = *reinterpret_cast<const float2*>(pin + (long long)(0 * kGroup + g) * kNPB);
        q1[g] = *reinterpret_cast<const float2*>(pin + (long long)(1 * kGroup + g) * kNPB);
    }

    // Consume queue (loaded 2 phases ago) -> spikes into smem buffer, then
    // refill the queue with phase gi+2's loads.
    auto consume_sts = [&](int gi, float2 (&q)[kGroup], int buf) {
        float* sb = sm + buf * kBufSize;
#pragma unroll
        for (int g = 0; g < kGroup; ++g) {
            float s0, s1;
            v0 += q[g].x; s0 = (v0 > kTh) ? 1.f : 0.f; v0 = (v0 > kTh) ? 0.f : v0;
            v1 += q[g].y; s1 = (v1 > kTh) ? 1.f : 0.f; v1 = (v1 > kTh) ? 0.f : v1;
            // banks (row + 2p)/(row + 2p + 1): half-warps on opposite
            // parities -> 32 distinct banks, conflict-free.
            sb[g * kTSlice + wbase + 0] = s0;
            sb[g * kTSlice + wbase + 1] = s1;
        }
        if (gi + 2 < kNG) {
            const float* pn = pin + (long long)(gi + 2) * kGroup * kNPB;
#pragma unroll
            for (int g = 0; g < kGroup; ++g)
                q[g] = *reinterpret_cast<const float2*>(pn + (long long)g * kNPB);
        }
    };

    auto lds_stg = [&](int gi, int buf) {
        const float* sb = sm + buf * kBufSize;
        float* po = pout + (long long)gi * kGroup * kNPB;
#pragma unroll
        for (int g = 0; g < kGroup; ++g) {
            float2 o;
            o.x = sb[g * kTSlice + rbase];       // bank (2p + row): conflict-free
            o.y = sb[g * kTSlice + rbase + 33];  // bank (2p + 1 + row)
            *reinterpret_cast<float2*>(po + (long long)g * kNPB) = o;
        }
    };

#pragma unroll 1
    for (int pi = 0; pi < 12; ++pi) {            // pairs cover phases 0..23
        const int gi = pi * 2;
        const int b0 = (pi & 1) * 2, b1 = b0 + 1;
        consume_sts(gi,     q0, b0);
        consume_sts(gi + 1, q1, b1);
        __syncthreads();                         // one barrier per 8 timesteps
        lds_stg(gi,     b0);
        lds_stg(gi + 1, b1);
    }
    // Tail phase 24 (buf 0: last overwritten in pair 10; pair 11's barrier
    // fences pair 10's reads from this write).
    consume_sts(kNG - 1, q0, 0);
    __syncthreads();
    lds_stg(kNG - 1, 0);
}

extern "C" void kernel_launch(void* const* d_in, const int* in_sizes, int n_in,
                              void* d_out, int out_size) {
    (void)in_sizes; (void)n_in; (void)out_size;
    const float* in = (const float*)d_in[0];
    float* out = (float*)d_out;
    static bool attr_done = false;
    if (!attr_done) {
        cudaFuncSetAttribute(integrator_kernel,
                             cudaFuncAttributeMaxDynamicSharedMemorySize,
                             kSmemBytes);
        attr_done = true;
    }
    dim3 grid(kWC / 32, kH / 32, 4 * 2);   // 16 x 2 x 8 = 256 blocks x 512 thr
    integrator_kernel<<<grid, 512, kSmemBytes>>>(in, out);
}